// round 1
// baseline (speedup 1.0000x reference)
#include <cuda_runtime.h>
#include <math.h>

#define NS 51
#define NITER 50
#define NT 64

// Lane packing per block: handles batch rows (row0,row1).
//   .x = mix-solve row0, .y = pure-solve row0, .z = mix row1, .w = pure row1
__global__ __launch_bounds__(NT) void cosmo_kernel(
    const float* __restrict__ my_g,    // [B,51]
    const float* __restrict__ vcomp,   // [B]
    const float* __restrict__ vtsig,   // [B,51,2]
    const float* __restrict__ vvt,     // [B]
    float* __restrict__ out,           // [B]
    int B)
{
    __shared__ float4 Hsh[2][NS];
    __shared__ float4 red[NT];

    const int t = threadIdx.x;
    const int row0 = blockIdx.x * 2;
    int row1 = row0 + 1;
    const bool w1 = (row1 < B);
    if (!w1) row1 = row0;

    // ---- Build SSS row (m = t) in registers; constants computed in double
    //      to match the numpy float64 -> float32 reference path. ----
    float S[NS];
    if (t < NS) {
        const double RT      = (8.3144598 / 4184.0) * 623.15;
        const double fpol    = (3.667 - 1.0) / (3.667 + 0.5);
        const double alpha_p = fpol * (0.3 * pow(7.5, 1.5) / 0.0002395);
        const double si = -0.025 + 0.001 * (double)t;
        #pragma unroll
        for (int j = 0; j < NS; j++) {
            const double sj = -0.025 + 0.001 * (double)j;
            const double smax = si > sj ? si : sj;
            const double smin = si > sj ? sj : si;
            double acc = smax - 0.0084; acc = acc > 0.0 ? acc : 0.0;
            double don = smin + 0.0084; don = don < 0.0 ? don : 0.0;
            const double ss = si + sj;
            const double dw = 0.5 * alpha_p * ss * ss + 85580.0 * acc * don;
            S[j] = expf((float)(-dw / RT));
        }
    }

    // ---- Load inputs for this thread's sigma index ----
    float my0 = 0.f, my1 = 0.f, vt0 = 0.f, vt1 = 0.f;
    if (t < NS) {
        my0 = my_g[row0 * NS + t];
        my1 = my_g[row1 * NS + t];
        vt0 = vtsig[(row0 * NS + t) * 2 + 1];
        vt1 = vtsig[(row1 * NS + t) * 2 + 1];
    }

    // ---- Block reduction: A0 = sum(my), A1 = sum(vt), for both rows ----
    red[t] = make_float4(my0, vt0, my1, vt1);
    __syncthreads();
    #pragma unroll
    for (int s = NT / 2; s > 0; s >>= 1) {
        if (t < s) {
            float4 a = red[t], b = red[t + s];
            red[t] = make_float4(a.x + b.x, a.y + b.y, a.z + b.z, a.w + b.w);
        }
        __syncthreads();
    }
    const float A00 = red[0].x, A10 = red[0].y;   // row0: sum(my), sum(vt)
    const float A01 = red[0].z, A11 = red[0].w;   // row1

    const float X0 = 0.235f, X1 = 1.0f - 0.235f;

    float4 P = make_float4(0.f, 0.f, 0.f, 0.f);
    if (t < NS) {
        const float dm0 = X0 * A00 + X1 * A10;
        const float dm1 = X0 * A01 + X1 * A11;
        P.x = (X0 * my0 + X1 * vt0) / dm0;   // psigma_mix row0
        P.y = my0 / A00;                     // psigma      row0
        P.z = (X0 * my1 + X1 * vt1) / dm1;   // psigma_mix row1
        P.w = my1 / A01;                     // psigma      row1
    }
    float4 G = make_float4(1.f, 1.f, 1.f, 1.f);

    // ---- 50-step damped fixed point, all 4 lanes at once ----
    #pragma unroll 1
    for (int it = 0; it < NITER; it++) {
        if (t < NS) {
            Hsh[it & 1][t] = make_float4(P.x * G.x, P.y * G.y, P.z * G.z, P.w * G.w);
        }
        __syncthreads();
        if (t < NS) {
            const float4* __restrict__ H = Hsh[it & 1];
            float ax = 0.f, ay = 0.f, az = 0.f, aw = 0.f;
            #pragma unroll
            for (int n = 0; n < NS; n++) {
                const float4 h = H[n];          // broadcast LDS.128
                ax = fmaf(S[n], h.x, ax);
                ay = fmaf(S[n], h.y, ay);
                az = fmaf(S[n], h.z, az);
                aw = fmaf(S[n], h.w, aw);
            }
            G.x = 0.5f * (__fdividef(1.f, ax) + G.x);
            G.y = 0.5f * (__fdividef(1.f, ay) + G.y);
            G.z = 0.5f * (__fdividef(1.f, az) + G.z);
            G.w = 0.5f * (__fdividef(1.f, aw) + G.w);
        }
    }

    // ---- Residual term reduction: sum_n psigma[n]*(lnG_mix - lnG_i) ----
    float c0 = 0.f, c1 = 0.f;
    if (t < NS) {
        c0 = P.y * (logf(G.x) - logf(G.y));
        c1 = P.w * (logf(G.z) - logf(G.w));
    }
    __syncthreads();
    red[t] = make_float4(c0, c1, 0.f, 0.f);
    __syncthreads();
    #pragma unroll
    for (int s = NT / 2; s > 0; s >>= 1) {
        if (t < s) {
            float4 a = red[t], b = red[t + s];
            red[t] = make_float4(a.x + b.x, a.y + b.y, 0.f, 0.f);
        }
        __syncthreads();
    }

    // ---- Scalar epilogue (Staverman-Guggenheim combinatorial) ----
    if (t == 0) {
        const float AEFF = 7.5f, Q0c = 79.53f, R0c = 66.69f;
        const float sums[2] = { red[0].x, red[0].y };
        const float A0s[2] = { A00, A01 };
        const float A1s[2] = { A10, A11 };
        const int   rows[2] = { row0, row1 };
        const int   nrows = w1 ? 2 : 1;
        for (int r = 0; r < nrows; r++) {
            const int   row = rows[r];
            const float A0 = A0s[r], A1 = A1s[r];
            const float lng_resid = A0 / AEFF * sums[r];
            const float q0 = A0 / Q0c, q1 = A1 / Q0c;
            const float r0 = vcomp[row] / R0c, r1 = vvt[row] / R0c;
            const float xq = X0 * q0 + X1 * q1;
            const float xr = X0 * r0 + X1 * r1;
            const float theta = X0 * q0 / xq;
            const float phi   = X0 * r0 / xr;
            const float l0 = 5.0f * (r0 - q0) - (r0 - 1.0f);
            const float l1 = 5.0f * (r1 - q1) - (r1 - 1.0f);
            const float xl = X0 * l0 + X1 * l1;
            const float lng_comb = logf(phi / X0) + 5.0f * q0 * logf(theta / phi)
                                   + l0 - phi / X0 * xl;
            out[row] = lng_resid + lng_comb;
        }
    }
}

extern "C" void kernel_launch(void* const* d_in, const int* in_sizes, int n_in,
                              void* d_out, int out_size)
{
    const int B = out_size;  // output is [B,1] float32
    // Identify inputs defensively by element count:
    //   my: 51*B, vt_sigma: 102*B, v_compound then v_vt: B each (dict order).
    const float* my = nullptr;
    const float* vt = nullptr;
    const float* vc = nullptr;
    const float* vv = nullptr;
    for (int i = 0; i < n_in; i++) {
        const long sz = in_sizes[i];
        if (sz == (long)B * NS)          my = (const float*)d_in[i];
        else if (sz == (long)B * NS * 2) vt = (const float*)d_in[i];
        else if (sz == (long)B) {
            if (!vc) vc = (const float*)d_in[i];
            else     vv = (const float*)d_in[i];
        }
    }
    const int blocks = (B + 1) / 2;
    cosmo_kernel<<<blocks, NT>>>(my, vc, vt, vv, (float*)d_out, B);
}

// round 5
// speedup vs baseline: 3.0571x; 3.0571x over previous
#include <cuda_runtime.h>
#include <math.h>

#define NS 51
#define NITER 50
#define NT 128

// ---------------- constexpr double math (compile-time SSS table) ----------------
// Marked __host__ __device__ so the function-local constexpr in the kernel is
// legal without --expt-relaxed-constexpr (which the harness doesn't pass).
// exp via range reduction + Horner polynomial with 1/k! literals.
// All intermediates are O(1e-13 .. 2): no constexpr-poisoning underflow.
constexpr __host__ __device__ double cexp_(double x) {
    const double LN2     = 0.6931471805599453094172321;
    const double INV_LN2 = 1.4426950408889634073599247;
    const double t = x * INV_LN2;
    const long   k = (long)(t >= 0.0 ? t + 0.5 : t - 0.5);
    const double r = x - (double)k * LN2;          // |r| <= ~0.347
    double s = 7.647163731819816e-13;              // 1/15!
    s = s * r + 1.1470745597729725e-11;            // 1/14!
    s = s * r + 1.6059043836821613e-10;            // 1/13!
    s = s * r + 2.08767569878681e-9;               // 1/12!
    s = s * r + 2.505210838544172e-8;              // 1/11!
    s = s * r + 2.755731922398589e-7;              // 1/10!
    s = s * r + 2.755731922398589e-6;              // 1/9!
    s = s * r + 2.48015873015873e-5;               // 1/8!
    s = s * r + 1.984126984126984e-4;              // 1/7!
    s = s * r + 1.388888888888889e-3;              // 1/6!
    s = s * r + 8.333333333333333e-3;              // 1/5!
    s = s * r + 4.1666666666666664e-2;             // 1/4!
    s = s * r + 1.6666666666666666e-1;             // 1/3!
    s = s * r + 0.5;                               // 1/2!
    s = s * r + 1.0;                               // 1/1!
    s = s * r + 1.0;                               // 1/0!
    double pw = 1.0;
    const double base = (k >= 0) ? 2.0 : 0.5;
    long kk = (k >= 0) ? k : -k;
    for (long i = 0; i < kk; i++) pw *= base;      // |k| <= ~28: exact, normal
    return s * pw;
}
constexpr __host__ __device__ double csqrt_(double x) {
    double g = (x > 1.0) ? x : 1.0;
    for (int i = 0; i < 64; i++) g = 0.5 * (g + x / g);
    return g;
}

struct STab { float v[NS][NS]; };

constexpr __host__ __device__ STab make_stab() {
    STab tb{};
    const double RT      = (8.3144598 / 4184.0) * 623.15;
    const double fpol    = (3.667 - 1.0) / (3.667 + 0.5);
    const double aeff15  = 7.5 * csqrt_(7.5);             // 7.5^1.5
    const double alpha_p = fpol * (0.3 * aeff15 / 0.0002395);
    for (int m = 0; m < NS; m++) {
        for (int n = 0; n < NS; n++) {
            const double si = -0.025 + 0.001 * (double)m;
            const double sj = -0.025 + 0.001 * (double)n;
            const double smax = (si > sj) ? si : sj;
            const double smin = (si > sj) ? sj : si;
            double acc = smax - 0.0084; if (acc < 0.0) acc = 0.0;
            double don = smin + 0.0084; if (don > 0.0) don = 0.0;
            const double ss = si + sj;
            const double dw = 0.5 * alpha_p * ss * ss + 85580.0 * acc * don;
            const float dwf = (float)dw;                  // mimic f64 -> f32 cast
            tb.v[m][n] = (float)cexp_(-(double)dwf / RT);
        }
    }
    return tb;
}

// ---------------- kernel: one thread per (batch row, solve) ----------------
// tid even -> mix solve, tid odd -> pure solve. Pair communicates via shfl.
__global__ __launch_bounds__(NT, 3) void cosmo_imm_kernel(
    const float* __restrict__ my_g,    // [B,51]
    const float* __restrict__ vcomp,   // [B]
    const float* __restrict__ vtsig,   // [B,51,2]
    const float* __restrict__ vvt,     // [B]
    float* __restrict__ out,           // [B]
    int B)
{
    // Function-local constexpr: with constant indices after full unroll, every
    // access folds to an FFMA immediate (no memory operand).
    constexpr STab STAB = make_stab();

    const int tid = blockIdx.x * NT + threadIdx.x;
    int row = tid >> 1;
    const bool isPure = (tid & 1);
    if (row >= B) row = B - 1;         // clamp; keep warp convergent for shfl

    const float X0 = 0.235f, X1 = 1.0f - 0.235f;

    float P[NS], H[NS], T[NS];

    float A0 = 0.f, A1 = 0.f;
    #pragma unroll
    for (int n = 0; n < NS; n++) { float m = my_g[row * NS + n]; T[n] = m; A0 += m; }
    #pragma unroll
    for (int n = 0; n < NS; n++) { float v = vtsig[(row * NS + n) * 2 + 1]; H[n] = v; A1 += v; }

    if (isPure) {
        const float inv = __fdividef(1.f, A0);
        #pragma unroll
        for (int n = 0; n < NS; n++) P[n] = T[n] * inv;
    } else {
        const float inv = __fdividef(1.f, X0 * A0 + X1 * A1);
        #pragma unroll
        for (int n = 0; n < NS; n++) P[n] = fmaf(X0, T[n], X1 * H[n]) * inv;
    }

    #pragma unroll
    for (int n = 0; n < NS; n++) H[n] = P[n];   // G=1 => H=P

    // 50-step damped Jacobi; SSS entries are instruction immediates (rt=1).
    #pragma unroll 1
    for (int it = 0; it < NITER; it++) {
        #pragma unroll
        for (int m = 0; m < NS; m++) {
            float a0 = 0.f, a1 = 0.f, a2 = 0.f, a3 = 0.f;   // ILP=4 vs lat=4
            #pragma unroll
            for (int n = 0; n < NS - 3; n += 4) {
                a0 = fmaf(STAB.v[m][n+0], H[n+0], a0);
                a1 = fmaf(STAB.v[m][n+1], H[n+1], a1);
                a2 = fmaf(STAB.v[m][n+2], H[n+2], a2);
                a3 = fmaf(STAB.v[m][n+3], H[n+3], a3);
            }
            a0 = fmaf(STAB.v[m][48], H[48], a0);
            a1 = fmaf(STAB.v[m][49], H[49], a1);
            a2 = fmaf(STAB.v[m][50], H[50], a2);
            const float acc = (a0 + a1) + (a2 + a3);
            T[m] = 0.5f * fmaf(P[m], __fdividef(1.f, acc), H[m]);
        }
        #pragma unroll
        for (int n = 0; n < NS; n++) H[n] = T[n];
    }

    // Residual: pure lane accumulates sum_n P_pure[n]*(lnG_mix[n]-lnG_pure[n]).
    float resid = 0.f;
    #pragma unroll
    for (int n = 0; n < NS; n++) {
        const float g  = logf(__fdividef(H[n], P[n]));        // lnGamma this lane
        const float gp = __shfl_xor_sync(0xffffffffu, g, 1);  // partner's lnGamma
        resid = fmaf(P[n], gp - g, resid);
    }

    if (isPure && (tid >> 1) < B) {
        const float AEFF = 7.5f, Q0c = 79.53f, R0c = 66.69f;
        const float lng_resid = A0 * (1.0f / AEFF) * resid;
        const float q0 = A0 / Q0c, q1 = A1 / Q0c;
        const float r0 = vcomp[row] / R0c, r1 = vvt[row] / R0c;
        const float xq = X0 * q0 + X1 * q1;
        const float xr = X0 * r0 + X1 * r1;
        const float theta = X0 * q0 / xq;
        const float phi   = X0 * r0 / xr;
        const float l0 = 5.0f * (r0 - q0) - (r0 - 1.0f);
        const float l1 = 5.0f * (r1 - q1) - (r1 - 1.0f);
        const float xl = X0 * l0 + X1 * l1;
        const float lng_comb = logf(phi / X0) + 5.0f * q0 * logf(theta / phi)
                               + l0 - phi / X0 * xl;
        out[row] = lng_resid + lng_comb;
    }
}

extern "C" void kernel_launch(void* const* d_in, const int* in_sizes, int n_in,
                              void* d_out, int out_size)
{
    const int B = out_size;  // output is [B,1] float32
    const float* my = nullptr;
    const float* vt = nullptr;
    const float* vc = nullptr;
    const float* vv = nullptr;
    for (int i = 0; i < n_in; i++) {
        const long sz = in_sizes[i];
        if (sz == (long)B * NS)          my = (const float*)d_in[i];
        else if (sz == (long)B * NS * 2) vt = (const float*)d_in[i];
        else if (sz == (long)B) {
            if (!vc) vc = (const float*)d_in[i];
            else     vv = (const float*)d_in[i];
        }
    }
    const long threads = 2L * B;
    const int blocks = (int)((threads + NT - 1) / NT);
    cosmo_imm_kernel<<<blocks, NT>>>(my, vc, vt, vv, (float*)d_out, B);
}